// round 13
// baseline (speedup 1.0000x reference)
#include <cuda_runtime.h>
#include <cuda_bf16.h>

// ---------------------------------------------------------------------------
// Problem constants
// ---------------------------------------------------------------------------
#define TT 40
#define BB 64
#define HH 256          // encoder hidden per direction
#define MM (TT*BB)      // 2560
#define VT 32000

typedef unsigned long long ull;
typedef unsigned int u32;

// ---------------------------------------------------------------------------
// Scratch (static device memory; no allocations allowed)
// ---------------------------------------------------------------------------
__device__ float g_xg[MM*2048];                     // gate pre-activations
__device__ __nv_bfloat16 g_ahi[MM*512];             // activation hi plane
__device__ __nv_bfloat16 g_alo[MM*512];             // activation lo plane
__device__ __nv_bfloat16 g_whi[VT*512];             // weight hi plane (shared)
__device__ __nv_bfloat16 g_wlo[VT*512];             // weight lo plane (shared)
__device__ float g_ht_enc[2][2][HH*BB];             // [phase][dir][u*64+b]
__device__ float g_ht_dec[2][512*BB];               // [phase][u*64+b]
__device__ float g_finh[2][BB*512];
__device__ float g_finc[2][BB*512];
__device__ unsigned g_bcnt[4] = {0, 0, 0, 0};
__device__ unsigned g_bgen[4] = {0, 0, 0, 0};

// ---------------------------------------------------------------------------
// f32x2 packed-FMA helpers (Blackwell FFMA2 — PTX only)  [recurrent kernels]
// ---------------------------------------------------------------------------
__device__ __forceinline__ ull pack2(float lo, float hi) {
    ull r; asm("mov.b64 %0, {%1, %2};" : "=l"(r) : "f"(lo), "f"(hi)); return r;
}
__device__ __forceinline__ ull dup2(float x) {
    ull r; asm("mov.b64 %0, {%1, %1};" : "=l"(r) : "f"(x)); return r;
}
__device__ __forceinline__ void fma2(ull& d, ull a, ull b) {
    asm("fma.rn.f32x2 %0, %1, %2, %0;" : "+l"(d) : "l"(a), "l"(b));
}
__device__ __forceinline__ float2 unpack2(ull v) {
    float2 r; asm("mov.b64 {%0, %1}, %2;" : "=f"(r.x), "=f"(r.y) : "l"(v)); return r;
}
__device__ __forceinline__ float sigf(float x)    { return 1.f / (1.f + __expf(-x)); }
__device__ __forceinline__ float tanhfast(float x){ return 2.f / (1.f + __expf(-2.f*x)) - 1.f; }

// ---------------------------------------------------------------------------
// Grid barrier (slot-indexed; all participating CTAs co-resident)
// ---------------------------------------------------------------------------
__device__ __forceinline__ void gridbar_s(int slot, int nb) {
    __syncthreads();
    if (threadIdx.x == 0) {
        unsigned g = *(volatile unsigned*)&g_bgen[slot];
        __threadfence();
        if (atomicAdd(&g_bcnt[slot], 1u) == (unsigned)(nb - 1)) {
            g_bcnt[slot] = 0;
            __threadfence();
            atomicAdd(&g_bgen[slot], 1u);
        } else {
            while (*(volatile unsigned*)&g_bgen[slot] == g) { }
        }
        __threadfence();
    }
    __syncthreads();
}

// ---------------------------------------------------------------------------
// PTX helpers (baseline features only — build targets sm_103, no 'a')
// ---------------------------------------------------------------------------
__device__ __forceinline__ u32 smem_u32(const void* p) {
    u32 a; asm("{ .reg .u64 t; cvta.to.shared.u64 t, %1; cvt.u32.u64 %0, t; }"
               : "=r"(a) : "l"(p));
    return a;
}
__device__ __forceinline__ void cp16(u32 s, const void* g) {
    asm volatile("cp.async.cg.shared.global [%0], [%1], 16;" :: "r"(s), "l"(g));
}
__device__ __forceinline__ void ldsm4(u32& a0, u32& a1, u32& a2, u32& a3, u32 addr) {
    asm volatile("ldmatrix.sync.aligned.m8n8.x4.shared.b16 {%0,%1,%2,%3}, [%4];"
                 : "=r"(a0), "=r"(a1), "=r"(a2), "=r"(a3) : "r"(addr));
}
__device__ __forceinline__ void ldsm2(u32& b0, u32& b1, u32 addr) {
    asm volatile("ldmatrix.sync.aligned.m8n8.x2.shared.b16 {%0,%1}, [%2];"
                 : "=r"(b0), "=r"(b1) : "r"(addr));
}
__device__ __forceinline__ void mma16816(float* c, const u32* a, const u32* b) {
    asm volatile("mma.sync.aligned.m16n8k16.row.col.f32.bf16.bf16.f32 "
                 "{%0,%1,%2,%3}, {%4,%5,%6,%7}, {%8,%9}, {%0,%1,%2,%3};"
                 : "+f"(c[0]), "+f"(c[1]), "+f"(c[2]), "+f"(c[3])
                 : "r"(a[0]), "r"(a[1]), "r"(a[2]), "r"(a[3]), "r"(b[0]), "r"(b[1]));
}

// ---------------------------------------------------------------------------
// Embedding gather -> split bf16 planes
// ---------------------------------------------------------------------------
__global__ void gather_split(const int* __restrict__ tok, const float* __restrict__ emb,
                             __nv_bfloat16* __restrict__ hi, __nv_bfloat16* __restrict__ lo) {
    int i = blockIdx.x;
    int t = threadIdx.x;  // 128 threads * float4 = 512 floats
    float4 v = ((const float4*)(emb + (size_t)tok[i] * 512))[t];
    __nv_bfloat16 h0 = __float2bfloat16_rn(v.x), h1 = __float2bfloat16_rn(v.y);
    __nv_bfloat16 h2 = __float2bfloat16_rn(v.z), h3 = __float2bfloat16_rn(v.w);
    size_t o2 = ((size_t)i * 512 + t * 4) >> 1;
    ((__nv_bfloat162*)hi)[o2]     = __halves2bfloat162(h0, h1);
    ((__nv_bfloat162*)hi)[o2 + 1] = __halves2bfloat162(h2, h3);
    ((__nv_bfloat162*)lo)[o2]     = __halves2bfloat162(
        __float2bfloat16_rn(v.x - __bfloat162float(h0)),
        __float2bfloat16_rn(v.y - __bfloat162float(h1)));
    ((__nv_bfloat162*)lo)[o2 + 1] = __halves2bfloat162(
        __float2bfloat16_rn(v.z - __bfloat162float(h2)),
        __float2bfloat16_rn(v.w - __bfloat162float(h3)));
}

// ---------------------------------------------------------------------------
// fp32 -> (hi,lo) bf16 split (weights)
// ---------------------------------------------------------------------------
__global__ void split_kernel(const float4* __restrict__ in,
                             __nv_bfloat16* __restrict__ hi,
                             __nv_bfloat16* __restrict__ lo, int n4) {
    int i = blockIdx.x * 256 + threadIdx.x;
    if (i >= n4) return;
    float4 v = in[i];
    __nv_bfloat16 h0 = __float2bfloat16_rn(v.x), h1 = __float2bfloat16_rn(v.y);
    __nv_bfloat16 h2 = __float2bfloat16_rn(v.z), h3 = __float2bfloat16_rn(v.w);
    ((__nv_bfloat162*)hi)[i * 2]     = __halves2bfloat162(h0, h1);
    ((__nv_bfloat162*)hi)[i * 2 + 1] = __halves2bfloat162(h2, h3);
    ((__nv_bfloat162*)lo)[i * 2]     = __halves2bfloat162(
        __float2bfloat16_rn(v.x - __bfloat162float(h0)),
        __float2bfloat16_rn(v.y - __bfloat162float(h1)));
    ((__nv_bfloat162*)lo)[i * 2 + 1] = __halves2bfloat162(
        __float2bfloat16_rn(v.z - __bfloat162float(h2)),
        __float2bfloat16_rn(v.w - __bfloat162float(h3)));
}

// ---------------------------------------------------------------------------
// mma.sync bf16 GEMM: C[M=2560, N] = A[M,512] * W[N,512]^T + bias,
// fp32-accurate via extended-K bf16 split (K' = 1536: Ah*Bh + Al*Bh + Ah*Bl).
// CTA tile 128x128, 8 warps (2M x 4N), warp tile 64x32 (4x4 HMMA.16816).
// BK=32, cp.async double buffer, smem row stride 40 bf16 (conflict-free ldmatrix).
// ---------------------------------------------------------------------------
#define ASTR 40                       // smem row stride (bf16); 80 bytes
#define NCHUNK 48                     // 3 planes * 512/32

__global__ __launch_bounds__(256, 2)
void gemm_mma(const __nv_bfloat16* __restrict__ Ahi, const __nv_bfloat16* __restrict__ Alo,
              const __nv_bfloat16* __restrict__ Whi, const __nv_bfloat16* __restrict__ Wlo,
              const float* __restrict__ bias, float* __restrict__ C, int N)
{
    __shared__ __nv_bfloat16 sA[2][128 * ASTR];
    __shared__ __nv_bfloat16 sB[2][128 * ASTR];

    int tid = threadIdx.x;
    int wid = tid >> 5, l = tid & 31;
    int wm = wid & 1, wn = wid >> 1;              // 2 x 4 warp grid
    int m0 = blockIdx.x * 128;                    // x fastest -> W-tile L2 reuse
    int n0 = blockIdx.y * 128;

    float acc[4][4][4];
#pragma unroll
    for (int i = 0; i < 4; i++)
#pragma unroll
        for (int j = 0; j < 4; j++)
#pragma unroll
            for (int q = 0; q < 4; q++) acc[i][j][q] = 0.f;

    int lr = tid >> 2, lsl = tid & 3;

    u32 sAu[2] = { smem_u32(sA[0]), smem_u32(sA[1]) };
    u32 sBu[2] = { smem_u32(sB[0]), smem_u32(sB[1]) };

    u32 aoff = (u32)((wm * 64 + (l & 15)) * ASTR * 2 + (l >> 4) * 16);
    u32 boff = (u32)((wn * 32 + (l & 7)) * ASTR * 2 + ((l >> 3) & 1) * 16);

    auto load_chunk = [&](int c, int buf) {
        int phs = c >> 4;                         // 0: hi*hi, 1: lo*hi, 2: hi*lo
        int kc  = (c & 15) * 32;
        const __nv_bfloat16* Ap = (phs == 1) ? Alo : Ahi;
        const __nv_bfloat16* Bp = (phs == 2) ? Wlo : Whi;
#pragma unroll
        for (int it = 0; it < 2; it++) {
            int r = lr + it * 64;
            u32 d = (u32)(r * ASTR * 2 + lsl * 16);
            cp16(sAu[buf] + d, Ap + ((size_t)(m0 + r) << 9) + kc + lsl * 8);
            cp16(sBu[buf] + d, Bp + ((size_t)(n0 + r) << 9) + kc + lsl * 8);
        }
        asm volatile("cp.async.commit_group;");
    };

    load_chunk(0, 0);
    for (int c = 0; c < NCHUNK; c++) {
        int buf = c & 1;
        if (c + 1 < NCHUNK) {
            load_chunk(c + 1, buf ^ 1);
            asm volatile("cp.async.wait_group 1;");
        } else {
            asm volatile("cp.async.wait_group 0;");
        }
        __syncthreads();
#pragma unroll
        for (int ks = 0; ks < 2; ks++) {
            u32 a[4][4], b[4][2];
#pragma unroll
            for (int i = 0; i < 4; i++)
                ldsm4(a[i][0], a[i][1], a[i][2], a[i][3],
                      sAu[buf] + aoff + i * (16 * ASTR * 2) + ks * 32);
#pragma unroll
            for (int j = 0; j < 4; j++)
                ldsm2(b[j][0], b[j][1],
                      sBu[buf] + boff + j * (8 * ASTR * 2) + ks * 32);
#pragma unroll
            for (int i = 0; i < 4; i++)
#pragma unroll
                for (int j = 0; j < 4; j++)
                    mma16816(acc[i][j], a[i], b[j]);
        }
        __syncthreads();
    }

    int mrow = m0 + wm * 64 + (l >> 2);
    int ncol = n0 + wn * 32 + (l & 3) * 2;
#pragma unroll
    for (int i = 0; i < 4; i++) {
        size_t mA = (size_t)(mrow + i * 16);
#pragma unroll
        for (int j = 0; j < 4; j++) {
            int n = ncol + j * 8;
            float b0 = bias[n], b1 = bias[n + 1];
            float2 v0 = make_float2(acc[i][j][0] + b0, acc[i][j][1] + b1);
            float2 v1 = make_float2(acc[i][j][2] + b0, acc[i][j][3] + b1);
            *(float2*)(C + mA * (size_t)N + n)       = v0;
            *(float2*)(C + (mA + 8) * (size_t)N + n) = v1;
        }
    }
}

// ---------------------------------------------------------------------------
// Encoder recurrent kernel (persistent). 128 CTAs x 1024 threads.
// Cell (b,u) computed by 4 threads (k-quarters) + smem reduction.
// Per-direction grid barriers (64 CTAs each).
// ---------------------------------------------------------------------------
#define ENC_SMEM (16384 + 256*68*4 + 16384)
__global__ __launch_bounds__(1024, 1)
void enc_rec(const float* __restrict__ xg, const float* __restrict__ Whh,
             const float* __restrict__ bhh,
             __nv_bfloat16* __restrict__ yhi, __nv_bfloat16* __restrict__ ylo,
             float* __restrict__ finh, float* __restrict__ finc) {
    extern __shared__ char smem[];
    float*  wsh = (float*)smem;                       // [256 k][4 u][4 gates]
    float*  hsh = (float*)(smem + 16384);             // [256][68] padded h^T
    float4* red = (float4*)(smem + 16384 + 256*68*4); // [1024] partials
    int tid = threadIdx.x;
    int q  = tid >> 8;              // k-quarter 0..3
    int r  = tid & 255;
    int ul = r >> 6;
    int b  = r & 63;
    int dir = blockIdx.x >> 6;
    int u0  = (blockIdx.x & 63) * 4;
    int u   = u0 + ul;
    const float* W = Whh + (size_t)dir * 1024 * 256;

    for (int idx = tid; idx < 16 * 256; idx += 1024) {
        int row = idx >> 8, k = idx & 255;
        int gate = row >> 2, uu = row & 3;
        wsh[(k * 4 + uu) * 4 + gate] = W[(size_t)(gate * 256 + u0 + uu) * 256 + k];
    }
    float bh0 = 0.f, bh1 = 0.f, bh2 = 0.f, bh3 = 0.f, c = 0.f;
    if (q == 0) {
        bh0 = bhh[dir * 1024 + u];
        bh1 = bhh[dir * 1024 + 256 + u];
        bh2 = bhh[dir * 1024 + 512 + u];
        bh3 = bhh[dir * 1024 + 768 + u];
        __stcg(&g_ht_enc[0][dir][u * 64 + b], 0.f);
    }
    const ulonglong2* w2 = (const ulonglong2*)wsh;
    int kbase = q * 64;
    gridbar_s(dir, 64);

    for (int step = 0; step < TT; step++) {
        int ph = step & 1;
        const float* hsrc = g_ht_enc[ph][dir];
        for (int f = tid; f < 256 * 16; f += 1024) {
            float4 v = __ldcg((const float4*)hsrc + f);
            *(float4*)&hsh[(f >> 4) * 68 + (f & 15) * 4] = v;
        }
        int t = dir ? (TT - 1 - step) : step;
        const float* xr = xg + ((size_t)t * 64 + b) * 2048 + dir * 1024;
        float x0 = 0.f, x1 = 0.f, x2 = 0.f, x3 = 0.f;
        if (q == 0) { x0 = xr[u]; x1 = xr[256 + u]; x2 = xr[512 + u]; x3 = xr[768 + u]; }
        __syncthreads();
        ull acc0 = 0ull, acc1 = 0ull;
#pragma unroll 8
        for (int kk = 0; kk < 64; kk++) {
            int k = kbase + kk;
            ull hd = dup2(hsh[k * 68 + b]);
            ulonglong2 wv = w2[k * 4 + ul];
            fma2(acc0, wv.x, hd);        // (i,f)
            fma2(acc1, wv.y, hd);        // (g,o)
        }
        float2 p0 = unpack2(acc0), p1 = unpack2(acc1);
        red[tid] = make_float4(p0.x, p0.y, p1.x, p1.y);
        __syncthreads();
        if (q == 0) {
            float4 s0 = red[r], s1 = red[r + 256], s2 = red[r + 512], s3 = red[r + 768];
            float gi = s0.x + s1.x + s2.x + s3.x + x0 + bh0;
            float gf = s0.y + s1.y + s2.y + s3.y + x1 + bh1;
            float gg = s0.z + s1.z + s2.z + s3.z + x2 + bh2;
            float go = s0.w + s1.w + s2.w + s3.w + x3 + bh3;
            c = sigf(gf) * c + sigf(gi) * tanhfast(gg);
            float h = sigf(go) * tanhfast(c);
            size_t off = ((size_t)t * 64 + b) * 512 + dir * 256 + u;
            __nv_bfloat16 hb = __float2bfloat16_rn(h);
            yhi[off] = hb;
            ylo[off] = __float2bfloat16_rn(h - __bfloat162float(hb));
            __stcg(&g_ht_enc[ph ^ 1][dir][u * 64 + b], h);
            if (step == TT - 1) {
                finh[b * 512 + dir * 256 + u] = h;
                finc[b * 512 + dir * 256 + u] = c;
            }
        }
        gridbar_s(dir, 64);
    }
}

// ---------------------------------------------------------------------------
// Decoder recurrent kernel. Hidden 512, gates 2048, K=512.
// 128 CTAs x 1024 threads; 4-way k-split + smem reduction.
// ---------------------------------------------------------------------------
#define DEC_SMEM (32768 + 512*68*4 + 16384)
__global__ __launch_bounds__(1024, 1)
void dec_rec(const float* __restrict__ xg, const float* __restrict__ Whh,
             const float* __restrict__ bhh, const float* __restrict__ h0,
             const float* __restrict__ c0,
             __nv_bfloat16* __restrict__ yhi, __nv_bfloat16* __restrict__ ylo) {
    extern __shared__ char smem[];
    float*  wsh = (float*)smem;                       // [512 k][4 u][4 gates]
    float*  hsh = (float*)(smem + 32768);             // [512][68]
    float4* red = (float4*)(smem + 32768 + 512*68*4); // [1024]
    int tid = threadIdx.x;
    int q  = tid >> 8;
    int r  = tid & 255;
    int ul = r >> 6;
    int b  = r & 63;
    int u0 = blockIdx.x * 4;
    int u  = u0 + ul;

    for (int idx = tid; idx < 16 * 512; idx += 1024) {
        int row = idx >> 9, k = idx & 511;
        int gate = row >> 2, uu = row & 3;
        wsh[(k * 4 + uu) * 4 + gate] = Whh[(size_t)(gate * 512 + u0 + uu) * 512 + k];
    }
    float bh0 = 0.f, bh1 = 0.f, bh2 = 0.f, bh3 = 0.f, c = 0.f;
    if (q == 0) {
        bh0 = bhh[u]; bh1 = bhh[512 + u]; bh2 = bhh[1024 + u]; bh3 = bhh[1536 + u];
        c = c0[b * 512 + u];
        __stcg(&g_ht_dec[0][u * 64 + b], h0[b * 512 + u]);
    }
    const ulonglong2* w2 = (const ulonglong2*)wsh;
    int kbase = q * 128;
    gridbar_s(2, 128);

    for (int step = 0; step < TT; step++) {
        int ph = step & 1;
        const float* hsrc = g_ht_dec[ph];
        for (int f = tid; f < 512 * 16; f += 1024) {
            float4 v = __ldcg((const float4*)hsrc + f);
            *(float4*)&hsh[(f >> 4) * 68 + (f & 15) * 4] = v;
        }
        const float* xr = xg + ((size_t)step * 64 + b) * 2048;
        float x0 = 0.f, x1 = 0.f, x2 = 0.f, x3 = 0.f;
        if (q == 0) { x0 = xr[u]; x1 = xr[512 + u]; x2 = xr[1024 + u]; x3 = xr[1536 + u]; }
        __syncthreads();
        ull acc0 = 0ull, acc1 = 0ull;
#pragma unroll 8
        for (int kk = 0; kk < 128; kk++) {
            int k = kbase + kk;
            ull hd = dup2(hsh[k * 68 + b]);
            ulonglong2 wv = w2[k * 4 + ul];
            fma2(acc0, wv.x, hd);
            fma2(acc1, wv.y, hd);
        }
        float2 p0 = unpack2(acc0), p1 = unpack2(acc1);
        red[tid] = make_float4(p0.x, p0.y, p1.x, p1.y);
        __syncthreads();
        if (q == 0) {
            float4 s0 = red[r], s1 = red[r + 256], s2 = red[r + 512], s3 = red[r + 768];
            float gi = s0.x + s1.x + s2.x + s3.x + x0 + bh0;
            float gf = s0.y + s1.y + s2.y + s3.y + x1 + bh1;
            float gg = s0.z + s1.z + s2.z + s3.z + x2 + bh2;
            float go = s0.w + s1.w + s2.w + s3.w + x3 + bh3;
            c = sigf(gf) * c + sigf(gi) * tanhfast(gg);
            float h = sigf(go) * tanhfast(c);
            size_t off = ((size_t)step * 64 + b) * 512 + u;
            __nv_bfloat16 hb = __float2bfloat16_rn(h);
            yhi[off] = hb;
            ylo[off] = __float2bfloat16_rn(h - __bfloat162float(hb));
            __stcg(&g_ht_dec[ph ^ 1][u * 64 + b], h);
        }
        gridbar_s(2, 128);
    }
}

// ---------------------------------------------------------------------------
// Host launcher
// ---------------------------------------------------------------------------
extern "C" void kernel_launch(void* const* d_in, const int* in_sizes, int n_in,
                              void* d_out, int out_size) {
    (void)in_sizes; (void)n_in; (void)out_size;
    const int*   src     = (const int*)  d_in[0];
    const int*   tgt     = (const int*)  d_in[1];
    const float* src_emb = (const float*)d_in[2];
    const float* tgt_emb = (const float*)d_in[3];
    const float* eWih    = (const float*)d_in[4];   // [2,2,1024,512]
    const float* eWhh    = (const float*)d_in[5];   // [2,2,1024,256]
    const float* ebih    = (const float*)d_in[6];   // [2,2,1024]
    const float* ebhh    = (const float*)d_in[7];
    const float* dWih    = (const float*)d_in[8];   // [2,2048,512]
    const float* dWhh    = (const float*)d_in[9];   // [2,2048,512]
    const float* dbih    = (const float*)d_in[10];
    const float* dbhh    = (const float*)d_in[11];
    const float* linW    = (const float*)d_in[12];  // [32000,512]
    const float* linb    = (const float*)d_in[13];
    float* out = (float*)d_out;

    cudaFuncSetAttribute(enc_rec, cudaFuncAttributeMaxDynamicSharedMemorySize, ENC_SMEM);
    cudaFuncSetAttribute(dec_rec, cudaFuncAttributeMaxDynamicSharedMemorySize, DEC_SMEM);

    float *pxg, *pfh, *pfc;
    __nv_bfloat16 *pahi, *palo, *pwhi, *pwlo;
    cudaGetSymbolAddress((void**)&pxg,  g_xg);
    cudaGetSymbolAddress((void**)&pfh,  g_finh);
    cudaGetSymbolAddress((void**)&pfc,  g_finc);
    cudaGetSymbolAddress((void**)&pahi, g_ahi);
    cudaGetSymbolAddress((void**)&palo, g_alo);
    cudaGetSymbolAddress((void**)&pwhi, g_whi);
    cudaGetSymbolAddress((void**)&pwlo, g_wlo);

    const int n4_small = 2048 * 512 / 4;    // 262144 -> 1024 blocks
    const int n4_lin   = VT * 512 / 4;      // 4096000 -> 16000 blocks

    // ---- encoder layer 1 ----
    gather_split<<<MM, 128>>>(src, src_emb, pahi, palo);
    split_kernel<<<(n4_small + 255) / 256, 256>>>((const float4*)eWih, pwhi, pwlo, n4_small);
    gemm_mma<<<dim3(20, 16), 256>>>(pahi, palo, pwhi, pwlo, ebih, pxg, 2048);
    enc_rec<<<128, 1024, ENC_SMEM>>>(pxg, eWhh, ebhh, pahi, palo, pfh, pfc);

    // ---- encoder layer 2 ----
    split_kernel<<<(n4_small + 255) / 256, 256>>>((const float4*)(eWih + 2 * 1024 * 512),
                                                  pwhi, pwlo, n4_small);
    gemm_mma<<<dim3(20, 16), 256>>>(pahi, palo, pwhi, pwlo, ebih + 2048, pxg, 2048);
    enc_rec<<<128, 1024, ENC_SMEM>>>(pxg, eWhh + 2 * 1024 * 256, ebhh + 2048,
                                     pahi, palo, pfh + BB * 512, pfc + BB * 512);

    // ---- decoder layer 1 ----
    gather_split<<<MM, 128>>>(tgt, tgt_emb, pahi, palo);
    split_kernel<<<(n4_small + 255) / 256, 256>>>((const float4*)dWih, pwhi, pwlo, n4_small);
    gemm_mma<<<dim3(20, 16), 256>>>(pahi, palo, pwhi, pwlo, dbih, pxg, 2048);
    dec_rec<<<128, 1024, DEC_SMEM>>>(pxg, dWhh, dbhh, pfh, pfc, pahi, palo);

    // ---- decoder layer 2 ----
    split_kernel<<<(n4_small + 255) / 256, 256>>>((const float4*)(dWih + 2048 * 512),
                                                  pwhi, pwlo, n4_small);
    gemm_mma<<<dim3(20, 16), 256>>>(pahi, palo, pwhi, pwlo, dbih + 2048, pxg, 2048);
    dec_rec<<<128, 1024, DEC_SMEM>>>(pxg, dWhh + 2048 * 512, dbhh + 2048,
                                     pfh + BB * 512, pfc + BB * 512, pahi, palo);

    // ---- output projection ----
    split_kernel<<<(n4_lin + 255) / 256, 256>>>((const float4*)linW, pwhi, pwlo, n4_lin);
    gemm_mma<<<dim3(20, 250), 256>>>(pahi, palo, pwhi, pwlo, linb, out, VT);
}

// round 14
// speedup vs baseline: 1.1795x; 1.1795x over previous
#include <cuda_runtime.h>
#include <cuda_bf16.h>

#define TT 40
#define BB 64
#define MM (TT*BB)      // 2560
#define VT 32000

typedef unsigned long long ull;
typedef unsigned int u32;
typedef __nv_bfloat16 bf16;

// ---------------------------------------------------------------------------
// Scratch (static device memory; no allocations allowed)
// ---------------------------------------------------------------------------
__device__ float g_xg[MM*2048];                          // gate pre-activations
__device__ __align__(16) bf16 g_ahi[MM*512];             // activation hi plane
__device__ __align__(16) bf16 g_alo[MM*512];             // activation lo plane
__device__ __align__(16) bf16 g_whi[VT*512];             // weight hi plane
__device__ __align__(16) bf16 g_wlo[VT*512];             // weight lo plane
__device__ __align__(16) bf16 g_he[2][2][2][64*256];     // [phase][dir][plane][b*256+u]
__device__ __align__(16) bf16 g_hd[2][2][64*512];        // [phase][plane][b*512+u]
__device__ float g_finh[2][BB*512];
__device__ float g_finc[2][BB*512];
__device__ unsigned g_bcnt[4] = {0, 0, 0, 0};
__device__ unsigned g_bgen[4] = {0, 0, 0, 0};

__device__ __forceinline__ float sigf(float x)    { return 1.f / (1.f + __expf(-x)); }
__device__ __forceinline__ float tanhfast(float x){ return 2.f / (1.f + __expf(-2.f*x)) - 1.f; }

// ---------------------------------------------------------------------------
// Grid barrier (slot-indexed; all participating CTAs co-resident)
// ---------------------------------------------------------------------------
__device__ __forceinline__ void gridbar_s(int slot, int nb) {
    __syncthreads();
    if (threadIdx.x == 0) {
        unsigned g = *(volatile unsigned*)&g_bgen[slot];
        __threadfence();
        if (atomicAdd(&g_bcnt[slot], 1u) == (unsigned)(nb - 1)) {
            g_bcnt[slot] = 0;
            __threadfence();
            atomicAdd(&g_bgen[slot], 1u);
        } else {
            while (*(volatile unsigned*)&g_bgen[slot] == g) { }
        }
        __threadfence();
    }
    __syncthreads();
}

// ---------------------------------------------------------------------------
// PTX helpers (baseline features only — build targets sm_103, no 'a')
// ---------------------------------------------------------------------------
__device__ __forceinline__ u32 smem_u32(const void* p) {
    u32 a; asm("{ .reg .u64 t; cvta.to.shared.u64 t, %1; cvt.u32.u64 %0, t; }"
               : "=r"(a) : "l"(p));
    return a;
}
__device__ __forceinline__ void cp16(u32 s, const void* g) {
    asm volatile("cp.async.cg.shared.global [%0], [%1], 16;" :: "r"(s), "l"(g));
}
__device__ __forceinline__ void ldsm4(u32& a0, u32& a1, u32& a2, u32& a3, u32 addr) {
    asm volatile("ldmatrix.sync.aligned.m8n8.x4.shared.b16 {%0,%1,%2,%3}, [%4];"
                 : "=r"(a0), "=r"(a1), "=r"(a2), "=r"(a3) : "r"(addr));
}
__device__ __forceinline__ void ldsm2(u32& b0, u32& b1, u32 addr) {
    asm volatile("ldmatrix.sync.aligned.m8n8.x2.shared.b16 {%0,%1}, [%2];"
                 : "=r"(b0), "=r"(b1) : "r"(addr));
}
__device__ __forceinline__ void mma16816(float* c, const u32* a, const u32* b) {
    asm volatile("mma.sync.aligned.m16n8k16.row.col.f32.bf16.bf16.f32 "
                 "{%0,%1,%2,%3}, {%4,%5,%6,%7}, {%8,%9}, {%0,%1,%2,%3};"
                 : "+f"(c[0]), "+f"(c[1]), "+f"(c[2]), "+f"(c[3])
                 : "r"(a[0]), "r"(a[1]), "r"(a[2]), "r"(a[3]), "r"(b[0]), "r"(b[1]));
}

// ---------------------------------------------------------------------------
// Embedding gather -> split bf16 planes
// ---------------------------------------------------------------------------
__global__ void gather_split(const int* __restrict__ tok, const float* __restrict__ emb,
                             bf16* __restrict__ hi, bf16* __restrict__ lo) {
    int i = blockIdx.x;
    int t = threadIdx.x;
    float4 v = ((const float4*)(emb + (size_t)tok[i] * 512))[t];
    bf16 h0 = __float2bfloat16_rn(v.x), h1 = __float2bfloat16_rn(v.y);
    bf16 h2 = __float2bfloat16_rn(v.z), h3 = __float2bfloat16_rn(v.w);
    size_t o2 = ((size_t)i * 512 + t * 4) >> 1;
    ((__nv_bfloat162*)hi)[o2]     = __halves2bfloat162(h0, h1);
    ((__nv_bfloat162*)hi)[o2 + 1] = __halves2bfloat162(h2, h3);
    ((__nv_bfloat162*)lo)[o2]     = __halves2bfloat162(
        __float2bfloat16_rn(v.x - __bfloat162float(h0)),
        __float2bfloat16_rn(v.y - __bfloat162float(h1)));
    ((__nv_bfloat162*)lo)[o2 + 1] = __halves2bfloat162(
        __float2bfloat16_rn(v.z - __bfloat162float(h2)),
        __float2bfloat16_rn(v.w - __bfloat162float(h3)));
}

// fp32 -> (hi,lo) bf16 split (weights)
__global__ void split_kernel(const float4* __restrict__ in,
                             bf16* __restrict__ hi, bf16* __restrict__ lo, int n4) {
    int i = blockIdx.x * 256 + threadIdx.x;
    if (i >= n4) return;
    float4 v = in[i];
    bf16 h0 = __float2bfloat16_rn(v.x), h1 = __float2bfloat16_rn(v.y);
    bf16 h2 = __float2bfloat16_rn(v.z), h3 = __float2bfloat16_rn(v.w);
    ((__nv_bfloat162*)hi)[i * 2]     = __halves2bfloat162(h0, h1);
    ((__nv_bfloat162*)hi)[i * 2 + 1] = __halves2bfloat162(h2, h3);
    ((__nv_bfloat162*)lo)[i * 2]     = __halves2bfloat162(
        __float2bfloat16_rn(v.x - __bfloat162float(h0)),
        __float2bfloat16_rn(v.y - __bfloat162float(h1)));
    ((__nv_bfloat162*)lo)[i * 2 + 1] = __halves2bfloat162(
        __float2bfloat16_rn(v.z - __bfloat162float(h2)),
        __float2bfloat16_rn(v.w - __bfloat162float(h3)));
}

// ---------------------------------------------------------------------------
// mma.sync bf16 GEMM (unchanged, proven): C = A*W^T + bias, ext-K split
// ---------------------------------------------------------------------------
#define ASTR 40
#define NCHUNK 48

__global__ __launch_bounds__(256, 2)
void gemm_mma(const bf16* __restrict__ Ahi, const bf16* __restrict__ Alo,
              const bf16* __restrict__ Whi, const bf16* __restrict__ Wlo,
              const float* __restrict__ bias, float* __restrict__ C, int N)
{
    __shared__ bf16 sA[2][128 * ASTR];
    __shared__ bf16 sB[2][128 * ASTR];

    int tid = threadIdx.x;
    int wid = tid >> 5, l = tid & 31;
    int wm = wid & 1, wn = wid >> 1;
    int m0 = blockIdx.x * 128;
    int n0 = blockIdx.y * 128;

    float acc[4][4][4];
#pragma unroll
    for (int i = 0; i < 4; i++)
#pragma unroll
        for (int j = 0; j < 4; j++)
#pragma unroll
            for (int q = 0; q < 4; q++) acc[i][j][q] = 0.f;

    int lr = tid >> 2, lsl = tid & 3;
    u32 sAu[2] = { smem_u32(sA[0]), smem_u32(sA[1]) };
    u32 sBu[2] = { smem_u32(sB[0]), smem_u32(sB[1]) };
    u32 aoff = (u32)((wm * 64 + (l & 15)) * ASTR * 2 + (l >> 4) * 16);
    u32 boff = (u32)((wn * 32 + (l & 7)) * ASTR * 2 + ((l >> 3) & 1) * 16);

    auto load_chunk = [&](int c, int buf) {
        int phs = c >> 4;
        int kc  = (c & 15) * 32;
        const bf16* Ap = (phs == 1) ? Alo : Ahi;
        const bf16* Bp = (phs == 2) ? Wlo : Whi;
#pragma unroll
        for (int it = 0; it < 2; it++) {
            int r = lr + it * 64;
            u32 d = (u32)(r * ASTR * 2 + lsl * 16);
            cp16(sAu[buf] + d, Ap + ((size_t)(m0 + r) << 9) + kc + lsl * 8);
            cp16(sBu[buf] + d, Bp + ((size_t)(n0 + r) << 9) + kc + lsl * 8);
        }
        asm volatile("cp.async.commit_group;");
    };

    load_chunk(0, 0);
    for (int c = 0; c < NCHUNK; c++) {
        int buf = c & 1;
        if (c + 1 < NCHUNK) {
            load_chunk(c + 1, buf ^ 1);
            asm volatile("cp.async.wait_group 1;");
        } else {
            asm volatile("cp.async.wait_group 0;");
        }
        __syncthreads();
#pragma unroll
        for (int ks = 0; ks < 2; ks++) {
            u32 a[4][4], b[4][2];
#pragma unroll
            for (int i = 0; i < 4; i++)
                ldsm4(a[i][0], a[i][1], a[i][2], a[i][3],
                      sAu[buf] + aoff + i * (16 * ASTR * 2) + ks * 32);
#pragma unroll
            for (int j = 0; j < 4; j++)
                ldsm2(b[j][0], b[j][1],
                      sBu[buf] + boff + j * (8 * ASTR * 2) + ks * 32);
#pragma unroll
            for (int i = 0; i < 4; i++)
#pragma unroll
                for (int j = 0; j < 4; j++)
                    mma16816(acc[i][j], a[i], b[j]);
        }
        __syncthreads();
    }

    int mrow = m0 + wm * 64 + (l >> 2);
    int ncol = n0 + wn * 32 + (l & 3) * 2;
#pragma unroll
    for (int i = 0; i < 4; i++) {
        size_t mA = (size_t)(mrow + i * 16);
#pragma unroll
        for (int j = 0; j < 4; j++) {
            int n = ncol + j * 8;
            float b0 = bias[n], b1 = bias[n + 1];
            float2 v0 = make_float2(acc[i][j][0] + b0, acc[i][j][1] + b1);
            float2 v1 = make_float2(acc[i][j][2] + b0, acc[i][j][3] + b1);
            *(float2*)(C + mA * (size_t)N + n)       = v0;
            *(float2*)(C + (mA + 8) * (size_t)N + n) = v1;
        }
    }
}

// ---------------------------------------------------------------------------
// Tensor-core recurrent kernels.
// Per CTA: 4 units (16 gate cols, gates reordered so cell's i,f,g,o adjacent).
// G[64b,16] = Hext @ Wext^T via m16n8k16; ext-K 3-term hi/lo split.
// 512 thr = 2 groups x 8 warps (warp grid 4M x 2N, warp tile 16x8); groups
// split ext-K chunks, combine G in smem. Whh split to smem bf16 once.
// A (H planes) reloaded per step from L2 via cp.async, gemm-identical layout.
// ---------------------------------------------------------------------------
#define SLOT_A 5120          // 64 rows * 40 bf16 * 2B
#define SLOT_W 1280          // 16 rows * 40 bf16 * 2B
#define ENC_SMEM (16*SLOT_A + 16*SLOT_W + 4096)   // 106496
#define DEC_SMEM (32*SLOT_A + 32*SLOT_W + 4096)   // 208896

__global__ __launch_bounds__(512, 1)
void enc_rec(const float* __restrict__ xg, const float* __restrict__ Whh,
             const float* __restrict__ bhh,
             bf16* __restrict__ yhi, bf16* __restrict__ ylo,
             float* __restrict__ finh, float* __restrict__ finc)
{
    extern __shared__ char sm[];
    char* Wb = sm + 16*SLOT_A;
    float* gsh = (float*)(sm + 16*SLOT_A + 16*SLOT_W);
    u32 Au = smem_u32(sm), Wu = smem_u32(Wb);
    int tid = threadIdx.x;
    int dir = blockIdx.x >> 6;
    int u0  = (blockIdx.x & 63) * 4;
    const float* W = Whh + (size_t)dir * 1024 * 256;

    // Whh -> smem bf16 hi/lo, chunk-slot layout (once)
    for (int idx = tid; idx < 16 * 256; idx += 512) {
        int n = idx >> 8, k = idx & 255;
        int grow = (n & 3) * 256 + u0 + (n >> 2);
        float w = W[(size_t)grow * 256 + k];
        bf16 h = __float2bfloat16_rn(w);
        int sb = (k >> 5) * SLOT_W + n * 80 + (k & 31) * 2;
        *(bf16*)(Wb + sb) = h;
        *(bf16*)(Wb + 8*SLOT_W + sb) = __float2bfloat16_rn(w - __bfloat162float(h));
    }
    int b = (tid & 255) >> 2, ul = tid & 3, u = u0 + ul;
    float bh0 = 0.f, bh1 = 0.f, bh2 = 0.f, bh3 = 0.f, c = 0.f;
    if (tid < 256) {
        bh0 = bhh[dir*1024 + u];        bh1 = bhh[dir*1024 + 256 + u];
        bh2 = bhh[dir*1024 + 512 + u];  bh3 = bhh[dir*1024 + 768 + u];
    }
    int grp = tid >> 8, w8 = (tid >> 5) & 7, l = tid & 31;
    int wm = w8 >> 1, wn = w8 & 1;
    u32 aoff = (u32)((wm*16 + (l & 15)) * 80 + (l >> 4) * 16);
    u32 boff = (u32)((wn*8 + (l & 7)) * 80 + ((l >> 3) & 1) * 16);
    int t2 = tid & 255, lr = t2 >> 2, lsl = t2 & 3;
    __syncthreads();

    for (int step = 0; step < TT; step++) {
        int ph = step & 1;
        int t = dir ? (TT - 1 - step) : step;
        float x0 = 0.f, x1 = 0.f, x2 = 0.f, x3 = 0.f;
        if (tid < 256) {
            const float* xr = xg + ((size_t)t * 64 + b) * 2048 + dir * 1024 + u;
            x0 = __ldcg(xr); x1 = __ldcg(xr + 256);
            x2 = __ldcg(xr + 512); x3 = __ldcg(xr + 768);
        }
        float acc[4] = {0.f, 0.f, 0.f, 0.f};
        if (step > 0) {
            const bf16* hp0 = g_he[ph][dir][0];
            const bf16* hp1 = g_he[ph][dir][1];
#pragma unroll
            for (int it = 0; it < 8; it++) {
                int cidx = grp + it * 2;
                const bf16* hp = (cidx < 8) ? hp0 : hp1;
                int kc = (cidx & 7) * 32;
                cp16(Au + cidx * SLOT_A + lr * 80 + lsl * 16, hp + lr * 256 + kc + lsl * 8);
            }
            asm volatile("cp.async.commit_group;");
            asm volatile("cp.async.wait_group 0;");
            __syncthreads();
#pragma unroll
            for (int cc = 0; cc < 12; cc++) {
                int cidx = grp * 12 + cc;
                int asl = (cidx < 16) ? cidx : cidx - 16;
                int wsl = (cidx < 8) ? cidx : cidx - 8;
                u32 Aa = Au + asl * SLOT_A + aoff;
                u32 Ba = Wu + wsl * SLOT_W + boff;
#pragma unroll
                for (int ks = 0; ks < 2; ks++) {
                    u32 a[4], bb[2];
                    ldsm4(a[0], a[1], a[2], a[3], Aa + ks * 32);
                    ldsm2(bb[0], bb[1], Ba + ks * 32);
                    mma16816(acc, a, bb);
                }
            }
        }
        int gr = wm * 16 + (l >> 2), gc = wn * 8 + (l & 3) * 2;
        if (grp == 0) {
            gsh[gr*16 + gc] = acc[0];       gsh[gr*16 + gc + 1] = acc[1];
            gsh[(gr+8)*16 + gc] = acc[2];   gsh[(gr+8)*16 + gc + 1] = acc[3];
        }
        __syncthreads();
        if (grp == 1) {
            gsh[gr*16 + gc] += acc[0];      gsh[gr*16 + gc + 1] += acc[1];
            gsh[(gr+8)*16 + gc] += acc[2];  gsh[(gr+8)*16 + gc + 1] += acc[3];
        }
        __syncthreads();
        if (tid < 256) {
            float4 gv = *(float4*)&gsh[b * 16 + ul * 4];
            float gi = gv.x + x0 + bh0, gf = gv.y + x1 + bh1;
            float gg = gv.z + x2 + bh2, go = gv.w + x3 + bh3;
            c = sigf(gf) * c + sigf(gi) * tanhfast(gg);
            float h = sigf(go) * tanhfast(c);
            bf16 hh = __float2bfloat16_rn(h);
            bf16 hl = __float2bfloat16_rn(h - __bfloat162float(hh));
            __stcg(&g_he[ph ^ 1][dir][0][b * 256 + u], hh);
            __stcg(&g_he[ph ^ 1][dir][1][b * 256 + u], hl);
            size_t off = ((size_t)t * 64 + b) * 512 + dir * 256 + u;
            yhi[off] = hh; ylo[off] = hl;
            if (step == TT - 1) {
                finh[b * 512 + dir * 256 + u] = h;
                finc[b * 512 + dir * 256 + u] = c;
            }
        }
        gridbar_s(dir, 64);
    }
}

__global__ __launch_bounds__(512, 1)
void dec_rec(const float* __restrict__ xg, const float* __restrict__ Whh,
             const float* __restrict__ bhh, const float* __restrict__ h0,
             const float* __restrict__ c0,
             bf16* __restrict__ yhi, bf16* __restrict__ ylo)
{
    extern __shared__ char sm[];
    char* Wb = sm + 32*SLOT_A;
    float* gsh = (float*)(sm + 32*SLOT_A + 32*SLOT_W);
    u32 Au = smem_u32(sm), Wu = smem_u32(Wb);
    int tid = threadIdx.x;
    int u0 = blockIdx.x * 4;

    for (int idx = tid; idx < 16 * 512; idx += 512) {
        int n = idx >> 9, k = idx & 511;
        int grow = (n & 3) * 512 + u0 + (n >> 2);
        float w = Whh[(size_t)grow * 512 + k];
        bf16 h = __float2bfloat16_rn(w);
        int sb = (k >> 5) * SLOT_W + n * 80 + (k & 31) * 2;
        *(bf16*)(Wb + sb) = h;
        *(bf16*)(Wb + 16*SLOT_W + sb) = __float2bfloat16_rn(w - __bfloat162float(h));
    }
    int b = (tid & 255) >> 2, ul = tid & 3, u = u0 + ul;
    float bh0 = 0.f, bh1 = 0.f, bh2 = 0.f, bh3 = 0.f, c = 0.f;
    if (tid < 256) {
        bh0 = bhh[u]; bh1 = bhh[512 + u]; bh2 = bhh[1024 + u]; bh3 = bhh[1536 + u];
        c = c0[b * 512 + u];
        float h = h0[b * 512 + u];
        bf16 hh = __float2bfloat16_rn(h);
        __stcg(&g_hd[0][0][b * 512 + u], hh);
        __stcg(&g_hd[0][1][b * 512 + u], __float2bfloat16_rn(h - __bfloat162float(hh)));
    }
    int grp = tid >> 8, w8 = (tid >> 5) & 7, l = tid & 31;
    int wm = w8 >> 1, wn = w8 & 1;
    u32 aoff = (u32)((wm*16 + (l & 15)) * 80 + (l >> 4) * 16);
    u32 boff = (u32)((wn*8 + (l & 7)) * 80 + ((l >> 3) & 1) * 16);
    int t2 = tid & 255, lr = t2 >> 2, lsl = t2 & 3;
    gridbar_s(2, 128);                      // h0 visible everywhere

    for (int step = 0; step < TT; step++) {
        int ph = step & 1;
        float x0 = 0.f, x1 = 0.f, x2 = 0.f, x3 = 0.f;
        if (tid < 256) {
            const float* xr = xg + ((size_t)step * 64 + b) * 2048 + u;
            x0 = __ldcg(xr); x1 = __ldcg(xr + 512);
            x2 = __ldcg(xr + 1024); x3 = __ldcg(xr + 1536);
        }
        const bf16* hp0 = g_hd[ph][0];
        const bf16* hp1 = g_hd[ph][1];
#pragma unroll
        for (int it = 0; it < 16; it++) {
            int cidx = grp + it * 2;
            const bf16* hp = (cidx < 16) ? hp0 : hp1;
            int kc = (cidx & 15) * 32;
            cp16(Au + cidx * SLOT_A + lr * 80 + lsl * 16, hp + lr * 512 + kc + lsl * 8);
        }
        asm volatile("cp.async.commit_group;");
        asm volatile("cp.async.wait_group 0;");
        __syncthreads();
        float acc[4] = {0.f, 0.f, 0.f, 0.f};
#pragma unroll
        for (int cc = 0; cc < 24; cc++) {
            int cidx = grp * 24 + cc;
            int asl = (cidx < 32) ? cidx : cidx - 32;
            int wsl = (cidx < 16) ? cidx : cidx - 16;
            u32 Aa = Au + asl * SLOT_A + aoff;
            u32 Ba = Wu + wsl * SLOT_W + boff;
#pragma unroll
            for (int ks = 0; ks < 2; ks++) {
                u32 a[4], bb[2];
                ldsm4(a[0], a[1], a[2], a[3], Aa + ks * 32);
                ldsm2(bb[0], bb[1], Ba + ks * 32);
                mma16816(acc, a, bb);
            }
        }
        int gr = wm * 16 + (l >> 2), gc = wn * 8 + (l & 3) * 2;
        if (grp == 0) {
            gsh[gr*16 + gc] = acc[0];       gsh[gr*16 + gc + 1] = acc[1];
            gsh[(gr+8)*16 + gc] = acc[2];   gsh[(gr+8)*16 + gc + 1] = acc[3];
        }
        __syncthreads();
        if (grp == 1) {
            gsh[gr*16 + gc] += acc[0];      gsh[gr*16 + gc + 1] += acc[1];
            gsh[(gr+8)*16 + gc] += acc[2];  gsh[(gr+8)*16 + gc + 1] += acc[3];
        }
        __syncthreads();
        if (tid < 256) {
            float4 gv = *(float4*)&gsh[b * 16 + ul * 4];
            float gi = gv.x + x0 + bh0, gf = gv.y + x1 + bh1;
            float gg = gv.z + x2 + bh2, go = gv.w + x3 + bh3;
            c = sigf(gf) * c + sigf(gi) * tanhfast(gg);
            float h = sigf(go) * tanhfast(c);
            bf16 hh = __float2bfloat16_rn(h);
            bf16 hl = __float2bfloat16_rn(h - __bfloat162float(hh));
            __stcg(&g_hd[ph ^ 1][0][b * 512 + u], hh);
            __stcg(&g_hd[ph ^ 1][1][b * 512 + u], hl);
            size_t off = ((size_t)step * 64 + b) * 512 + u;
            yhi[off] = hh; ylo[off] = hl;
        }
        gridbar_s(2, 128);
    }
}

// ---------------------------------------------------------------------------
// Host launcher
// ---------------------------------------------------------------------------
extern "C" void kernel_launch(void* const* d_in, const int* in_sizes, int n_in,
                              void* d_out, int out_size) {
    (void)in_sizes; (void)n_in; (void)out_size;
    const int*   src     = (const int*)  d_in[0];
    const int*   tgt     = (const int*)  d_in[1];
    const float* src_emb = (const float*)d_in[2];
    const float* tgt_emb = (const float*)d_in[3];
    const float* eWih    = (const float*)d_in[4];
    const float* eWhh    = (const float*)d_in[5];
    const float* ebih    = (const float*)d_in[6];
    const float* ebhh    = (const float*)d_in[7];
    const float* dWih    = (const float*)d_in[8];
    const float* dWhh    = (const float*)d_in[9];
    const float* dbih    = (const float*)d_in[10];
    const float* dbhh    = (const float*)d_in[11];
    const float* linW    = (const float*)d_in[12];
    const float* linb    = (const float*)d_in[13];
    float* out = (float*)d_out;

    cudaFuncSetAttribute(enc_rec, cudaFuncAttributeMaxDynamicSharedMemorySize, ENC_SMEM);
    cudaFuncSetAttribute(dec_rec, cudaFuncAttributeMaxDynamicSharedMemorySize, DEC_SMEM);

    float *pxg, *pfh, *pfc;
    bf16 *pahi, *palo, *pwhi, *pwlo;
    cudaGetSymbolAddress((void**)&pxg,  g_xg);
    cudaGetSymbolAddress((void**)&pfh,  g_finh);
    cudaGetSymbolAddress((void**)&pfc,  g_finc);
    cudaGetSymbolAddress((void**)&pahi, g_ahi);
    cudaGetSymbolAddress((void**)&palo, g_alo);
    cudaGetSymbolAddress((void**)&pwhi, g_whi);
    cudaGetSymbolAddress((void**)&pwlo, g_wlo);

    const int n4_small = 2048 * 512 / 4;
    const int n4_lin   = VT * 512 / 4;

    // ---- encoder layer 1 ----
    gather_split<<<MM, 128>>>(src, src_emb, pahi, palo);
    split_kernel<<<(n4_small + 255) / 256, 256>>>((const float4*)eWih, pwhi, pwlo, n4_small);
    gemm_mma<<<dim3(20, 16), 256>>>(pahi, palo, pwhi, pwlo, ebih, pxg, 2048);
    enc_rec<<<128, 512, ENC_SMEM>>>(pxg, eWhh, ebhh, pahi, palo, pfh, pfc);

    // ---- encoder layer 2 ----
    split_kernel<<<(n4_small + 255) / 256, 256>>>((const float4*)(eWih + 2 * 1024 * 512),
                                                  pwhi, pwlo, n4_small);
    gemm_mma<<<dim3(20, 16), 256>>>(pahi, palo, pwhi, pwlo, ebih + 2048, pxg, 2048);
    enc_rec<<<128, 512, ENC_SMEM>>>(pxg, eWhh + 2 * 1024 * 256, ebhh + 2048,
                                    pahi, palo, pfh + BB * 512, pfc + BB * 512);

    // ---- decoder layer 1 ----
    gather_split<<<MM, 128>>>(tgt, tgt_emb, pahi, palo);
    split_kernel<<<(n4_small + 255) / 256, 256>>>((const float4*)dWih, pwhi, pwlo, n4_small);
    gemm_mma<<<dim3(20, 16), 256>>>(pahi, palo, pwhi, pwlo, dbih, pxg, 2048);
    dec_rec<<<128, 512, DEC_SMEM>>>(pxg, dWhh, dbhh, pfh, pfc, pahi, palo);

    // ---- decoder layer 2 ----
    split_kernel<<<(n4_small + 255) / 256, 256>>>((const float4*)(dWih + 2048 * 512),
                                                  pwhi, pwlo, n4_small);
    gemm_mma<<<dim3(20, 16), 256>>>(pahi, palo, pwhi, pwlo, dbih + 2048, pxg, 2048);
    dec_rec<<<128, 512, DEC_SMEM>>>(pxg, dWhh + 2048 * 512, dbhh + 2048,
                                    pfh + BB * 512, pfc + BB * 512, pahi, palo);

    // ---- output projection ----
    split_kernel<<<(n4_lin + 255) / 256, 256>>>((const float4*)linW, pwhi, pwlo, n4_lin);
    gemm_mma<<<dim3(20, 250), 256>>>(pahi, palo, pwhi, pwlo, linb, out, VT);
}

// round 16
// speedup vs baseline: 1.2334x; 1.0457x over previous
#include <cuda_runtime.h>
#include <cuda_bf16.h>

#define TT 40
#define BB 64
#define MM (TT*BB)      // 2560
#define VT 32000

typedef unsigned long long ull;
typedef unsigned int u32;
typedef __nv_bfloat16 bf16;

// ---------------------------------------------------------------------------
// Scratch (static device memory; no allocations allowed)
// ---------------------------------------------------------------------------
__device__ float g_xg[MM*2048];                          // gate pre-activations
__device__ __align__(16) bf16 g_ahi[MM*512];             // activation hi plane
__device__ __align__(16) bf16 g_alo[MM*512];             // activation lo plane
__device__ __align__(16) bf16 g_whi[VT*512];             // weight hi plane
__device__ __align__(16) bf16 g_wlo[VT*512];             // weight lo plane
__device__ __align__(16) bf16 g_he[2][2][2][64*256];     // [phase][dir][plane][b*256+u]
__device__ __align__(16) bf16 g_hd[2][2][64*512];        // [phase][plane][b*512+u]
__device__ float g_finh[2][BB*512];
__device__ float g_finc[2][BB*512];
__device__ __align__(128) unsigned g_cnt[4][32];         // one 128B line per slot
__device__ __align__(128) unsigned g_exi[4][32];

__device__ __forceinline__ float sigf(float x)    { return 1.f / (1.f + __expf(-x)); }
__device__ __forceinline__ float tanhfast(float x){ return 2.f / (1.f + __expf(-2.f*x)) - 1.f; }

// ---------------------------------------------------------------------------
// Monotone-counter grid barrier: red.release arrival, ld.acquire poll.
// Counter only grows during the launch; reset at kernel end via exit counter.
// ---------------------------------------------------------------------------
__device__ __forceinline__ void mbar(unsigned* cnt, unsigned tgt) {
    __syncthreads();
    if (threadIdx.x == 0) {
        asm volatile("red.release.gpu.global.add.u32 [%0], %1;"
                     :: "l"(cnt), "r"(1u) : "memory");
        unsigned v;
        do {
            asm volatile("ld.acquire.gpu.global.u32 %0, [%1];"
                         : "=r"(v) : "l"(cnt) : "memory");
        } while (v < tgt);
    }
    __syncthreads();
}
__device__ __forceinline__ void mbar_reset(unsigned* cnt, unsigned* exi,
                                           int nb, bool leader) {
    __syncthreads();
    if (threadIdx.x == 0) {
        asm volatile("red.release.gpu.global.add.u32 [%0], %1;"
                     :: "l"(exi), "r"(1u) : "memory");
        if (leader) {
            unsigned v;
            do {
                asm volatile("ld.acquire.gpu.global.u32 %0, [%1];"
                             : "=r"(v) : "l"(exi) : "memory");
            } while (v < (unsigned)nb);
            *(volatile unsigned*)cnt = 0u;
            *(volatile unsigned*)exi = 0u;
            __threadfence();
        }
    }
}

// ---------------------------------------------------------------------------
// PTX helpers (baseline features only — build targets sm_103, no 'a')
// ---------------------------------------------------------------------------
__device__ __forceinline__ u32 smem_u32(const void* p) {
    u32 a; asm("{ .reg .u64 t; cvta.to.shared.u64 t, %1; cvt.u32.u64 %0, t; }"
               : "=r"(a) : "l"(p));
    return a;
}
__device__ __forceinline__ void cp16(u32 s, const void* g) {
    asm volatile("cp.async.cg.shared.global [%0], [%1], 16;" :: "r"(s), "l"(g));
}
__device__ __forceinline__ void ldsm4(u32& a0, u32& a1, u32& a2, u32& a3, u32 addr) {
    asm volatile("ldmatrix.sync.aligned.m8n8.x4.shared.b16 {%0,%1,%2,%3}, [%4];"
                 : "=r"(a0), "=r"(a1), "=r"(a2), "=r"(a3) : "r"(addr));
}
__device__ __forceinline__ void ldsm2(u32& b0, u32& b1, u32 addr) {
    asm volatile("ldmatrix.sync.aligned.m8n8.x2.shared.b16 {%0,%1}, [%2];"
                 : "=r"(b0), "=r"(b1) : "r"(addr));
}
__device__ __forceinline__ void mma16816(float* c, const u32* a, const u32* b) {
    asm volatile("mma.sync.aligned.m16n8k16.row.col.f32.bf16.bf16.f32 "
                 "{%0,%1,%2,%3}, {%4,%5,%6,%7}, {%8,%9}, {%0,%1,%2,%3};"
                 : "+f"(c[0]), "+f"(c[1]), "+f"(c[2]), "+f"(c[3])
                 : "r"(a[0]), "r"(a[1]), "r"(a[2]), "r"(a[3]), "r"(b[0]), "r"(b[1]));
}

// ---------------------------------------------------------------------------
// Embedding gather -> split bf16 planes
// ---------------------------------------------------------------------------
__global__ void gather_split(const int* __restrict__ tok, const float* __restrict__ emb,
                             bf16* __restrict__ hi, bf16* __restrict__ lo) {
    int i = blockIdx.x;
    int t = threadIdx.x;
    float4 v = ((const float4*)(emb + (size_t)tok[i] * 512))[t];
    bf16 h0 = __float2bfloat16_rn(v.x), h1 = __float2bfloat16_rn(v.y);
    bf16 h2 = __float2bfloat16_rn(v.z), h3 = __float2bfloat16_rn(v.w);
    size_t o2 = ((size_t)i * 512 + t * 4) >> 1;
    ((__nv_bfloat162*)hi)[o2]     = __halves2bfloat162(h0, h1);
    ((__nv_bfloat162*)hi)[o2 + 1] = __halves2bfloat162(h2, h3);
    ((__nv_bfloat162*)lo)[o2]     = __halves2bfloat162(
        __float2bfloat16_rn(v.x - __bfloat162float(h0)),
        __float2bfloat16_rn(v.y - __bfloat162float(h1)));
    ((__nv_bfloat162*)lo)[o2 + 1] = __halves2bfloat162(
        __float2bfloat16_rn(v.z - __bfloat162float(h2)),
        __float2bfloat16_rn(v.w - __bfloat162float(h3)));
}

// fp32 -> (hi,lo) bf16 split (weights)
__global__ void split_kernel(const float4* __restrict__ in,
                             bf16* __restrict__ hi, bf16* __restrict__ lo, int n4) {
    int i = blockIdx.x * 256 + threadIdx.x;
    if (i >= n4) return;
    float4 v = in[i];
    bf16 h0 = __float2bfloat16_rn(v.x), h1 = __float2bfloat16_rn(v.y);
    bf16 h2 = __float2bfloat16_rn(v.z), h3 = __float2bfloat16_rn(v.w);
    ((__nv_bfloat162*)hi)[i * 2]     = __halves2bfloat162(h0, h1);
    ((__nv_bfloat162*)hi)[i * 2 + 1] = __halves2bfloat162(h2, h3);
    ((__nv_bfloat162*)lo)[i * 2]     = __halves2bfloat162(
        __float2bfloat16_rn(v.x - __bfloat162float(h0)),
        __float2bfloat16_rn(v.y - __bfloat162float(h1)));
    ((__nv_bfloat162*)lo)[i * 2 + 1] = __halves2bfloat162(
        __float2bfloat16_rn(v.z - __bfloat162float(h2)),
        __float2bfloat16_rn(v.w - __bfloat162float(h3)));
}

// ---------------------------------------------------------------------------
// mma.sync bf16 GEMM (unchanged, proven): C = A*W^T + bias, ext-K split
// ---------------------------------------------------------------------------
#define ASTR 40
#define NCHUNK 48

__global__ __launch_bounds__(256, 2)
void gemm_mma(const bf16* __restrict__ Ahi, const bf16* __restrict__ Alo,
              const bf16* __restrict__ Whi, const bf16* __restrict__ Wlo,
              const float* __restrict__ bias, float* __restrict__ C, int N)
{
    __shared__ bf16 sA[2][128 * ASTR];
    __shared__ bf16 sB[2][128 * ASTR];

    int tid = threadIdx.x;
    int wid = tid >> 5, l = tid & 31;
    int wm = wid & 1, wn = wid >> 1;
    int m0 = blockIdx.x * 128;
    int n0 = blockIdx.y * 128;

    float acc[4][4][4];
#pragma unroll
    for (int i = 0; i < 4; i++)
#pragma unroll
        for (int j = 0; j < 4; j++)
#pragma unroll
            for (int q = 0; q < 4; q++) acc[i][j][q] = 0.f;

    int lr = tid >> 2, lsl = tid & 3;
    u32 sAu[2] = { smem_u32(sA[0]), smem_u32(sA[1]) };
    u32 sBu[2] = { smem_u32(sB[0]), smem_u32(sB[1]) };
    u32 aoff = (u32)((wm * 64 + (l & 15)) * ASTR * 2 + (l >> 4) * 16);
    u32 boff = (u32)((wn * 32 + (l & 7)) * ASTR * 2 + ((l >> 3) & 1) * 16);

    auto load_chunk = [&](int c, int buf) {
        int phs = c >> 4;
        int kc  = (c & 15) * 32;
        const bf16* Ap = (phs == 1) ? Alo : Ahi;
        const bf16* Bp = (phs == 2) ? Wlo : Whi;
#pragma unroll
        for (int it = 0; it < 2; it++) {
            int r = lr + it * 64;
            u32 d = (u32)(r * ASTR * 2 + lsl * 16);
            cp16(sAu[buf] + d, Ap + ((size_t)(m0 + r) << 9) + kc + lsl * 8);
            cp16(sBu[buf] + d, Bp + ((size_t)(n0 + r) << 9) + kc + lsl * 8);
        }
        asm volatile("cp.async.commit_group;");
    };

    load_chunk(0, 0);
    for (int c = 0; c < NCHUNK; c++) {
        int buf = c & 1;
        if (c + 1 < NCHUNK) {
            load_chunk(c + 1, buf ^ 1);
            asm volatile("cp.async.wait_group 1;");
        } else {
            asm volatile("cp.async.wait_group 0;");
        }
        __syncthreads();
#pragma unroll
        for (int ks = 0; ks < 2; ks++) {
            u32 a[4][4], b[4][2];
#pragma unroll
            for (int i = 0; i < 4; i++)
                ldsm4(a[i][0], a[i][1], a[i][2], a[i][3],
                      sAu[buf] + aoff + i * (16 * ASTR * 2) + ks * 32);
#pragma unroll
            for (int j = 0; j < 4; j++)
                ldsm2(b[j][0], b[j][1],
                      sBu[buf] + boff + j * (8 * ASTR * 2) + ks * 32);
#pragma unroll
            for (int i = 0; i < 4; i++)
#pragma unroll
                for (int j = 0; j < 4; j++)
                    mma16816(acc[i][j], a[i], b[j]);
        }
        __syncthreads();
    }

    int mrow = m0 + wm * 64 + (l >> 2);
    int ncol = n0 + wn * 32 + (l & 3) * 2;
#pragma unroll
    for (int i = 0; i < 4; i++) {
        size_t mA = (size_t)(mrow + i * 16);
#pragma unroll
        for (int j = 0; j < 4; j++) {
            int n = ncol + j * 8;
            float b0 = bias[n], b1 = bias[n + 1];
            float2 v0 = make_float2(acc[i][j][0] + b0, acc[i][j][1] + b1);
            float2 v1 = make_float2(acc[i][j][2] + b0, acc[i][j][3] + b1);
            *(float2*)(C + mA * (size_t)N + n)       = v0;
            *(float2*)(C + (mA + 8) * (size_t)N + n) = v1;
        }
    }
}

// ---------------------------------------------------------------------------
// Encoder recurrence: 64 CTAs (32/dir), 8 units/CTA (32 gate cols).
// G[64,32] = Hext @ Wext^T (ext-K 768) on m16n8k16; 512 thr = 2 groups x 8 warps
// (4M x 2N, warp tile 16x16 = two n8 tiles). Single-sync group reduction.
// ---------------------------------------------------------------------------
#define SLOT_A 5120              // 64 rows * 80B
#define ESLOT_W 2560             // 32 rows * 80B
#define ENC_SMEM (16*SLOT_A + 16*ESLOT_W + 16384)   // 139264
__global__ __launch_bounds__(512, 1)
void enc_rec(const float* __restrict__ xg, const float* __restrict__ Whh,
             const float* __restrict__ bhh,
             bf16* __restrict__ yhi, bf16* __restrict__ ylo,
             float* __restrict__ finh, float* __restrict__ finc)
{
    extern __shared__ char sm[];
    char* Wb = sm + 16*SLOT_A;
    float* gsh = (float*)(sm + 16*SLOT_A + 16*ESLOT_W);   // [2][2048]
    u32 Au = smem_u32(sm), Wu = smem_u32(Wb);
    int tid = threadIdx.x;
    int dir = blockIdx.x >> 5;
    int u0  = (blockIdx.x & 31) * 8;
    const float* W = Whh + (size_t)dir * 1024 * 256;

    // Whh -> smem bf16 hi/lo (once). col n: unit=n>>2, gate=n&3
    for (int idx = tid; idx < 32 * 256; idx += 512) {
        int n = idx >> 8, k = idx & 255;
        int grow = (n & 3) * 256 + u0 + (n >> 2);
        float w = W[(size_t)grow * 256 + k];
        bf16 h = __float2bfloat16_rn(w);
        int sb = (k >> 5) * ESLOT_W + n * 80 + (k & 31) * 2;
        *(bf16*)(Wb + sb) = h;
        *(bf16*)(Wb + 8*ESLOT_W + sb) = __float2bfloat16_rn(w - __bfloat162float(h));
    }
    int b = tid >> 3, ul = tid & 7, u = u0 + ul;
    float bh0 = bhh[dir*1024 + u],        bh1 = bhh[dir*1024 + 256 + u];
    float bh2 = bhh[dir*1024 + 512 + u],  bh3 = bhh[dir*1024 + 768 + u];
    float c = 0.f;

    int grp = tid >> 8, w8 = (tid >> 5) & 7, l = tid & 31;
    int wm = w8 >> 1, wn = w8 & 1;
    u32 aoff  = (u32)((wm*16 + (l & 15)) * 80 + (l >> 4) * 16);
    u32 boff0 = (u32)((wn*16 + (l & 7)) * 80 + ((l >> 3) & 1) * 16);
    u32 boff1 = boff0 + 8 * 80;
    int t2 = tid & 255, lr = t2 >> 2, lsl = t2 & 3;
    unsigned* cnt = &g_cnt[dir][0];
    unsigned tgt = 0;
    __syncthreads();

    for (int step = 0; step < TT; step++) {
        int ph = step & 1;
        int t = dir ? (TT - 1 - step) : step;
        if (step > 0) {                              // issue H loads first
            const bf16* hp0 = g_he[ph][dir][0];
            const bf16* hp1 = g_he[ph][dir][1];
#pragma unroll
            for (int it = 0; it < 8; it++) {
                int cidx = grp + it * 2;
                const bf16* hp = (cidx < 8) ? hp0 : hp1;
                int kc = (cidx & 7) * 32;
                cp16(Au + cidx * SLOT_A + lr * 80 + lsl * 16, hp + lr * 256 + kc + lsl * 8);
            }
            asm volatile("cp.async.commit_group;");
        }
        const float* xr = xg + ((size_t)t * 64 + b) * 2048 + dir * 1024 + u;
        float x0 = __ldcg(xr),        x1 = __ldcg(xr + 256);
        float x2 = __ldcg(xr + 512),  x3 = __ldcg(xr + 768);

        float acc0[4] = {0.f,0.f,0.f,0.f}, acc1[4] = {0.f,0.f,0.f,0.f};
        if (step > 0) {
            asm volatile("cp.async.wait_group 0;");
            __syncthreads();
#pragma unroll
            for (int cc = 0; cc < 12; cc++) {
                int cidx = grp * 12 + cc;
                int asl = (cidx < 16) ? cidx : cidx - 16;
                int wsl = (cidx < 8) ? cidx : cidx - 8;
                u32 Aa = Au + asl * SLOT_A + aoff;
                u32 Ba = Wu + wsl * ESLOT_W;
#pragma unroll
                for (int ks = 0; ks < 2; ks++) {
                    u32 a[4], bb0[2], bb1[2];
                    ldsm4(a[0], a[1], a[2], a[3], Aa + ks * 32);
                    ldsm2(bb0[0], bb0[1], Ba + boff0 + ks * 32);
                    ldsm2(bb1[0], bb1[1], Ba + boff1 + ks * 32);
                    mma16816(acc0, a, bb0);
                    mma16816(acc1, a, bb1);
                }
            }
        }
        // group-partial G into disjoint regions; one sync; consumer adds
        {
            float* gs = gsh + grp * 2048;
            int gr = wm * 16 + (l >> 2);
            int gc0 = wn * 16 + (l & 3) * 2, gc1 = gc0 + 8;
            gs[gr*32 + gc0] = acc0[0];        gs[gr*32 + gc0 + 1] = acc0[1];
            gs[(gr+8)*32 + gc0] = acc0[2];    gs[(gr+8)*32 + gc0 + 1] = acc0[3];
            gs[gr*32 + gc1] = acc1[0];        gs[gr*32 + gc1 + 1] = acc1[1];
            gs[(gr+8)*32 + gc1] = acc1[2];    gs[(gr+8)*32 + gc1 + 1] = acc1[3];
        }
        __syncthreads();
        {
            float4 a0 = *(float4*)&gsh[b * 32 + ul * 4];
            float4 a1 = *(float4*)&gsh[2048 + b * 32 + ul * 4];
            float gi = a0.x + a1.x + x0 + bh0;
            float gf = a0.y + a1.y + x1 + bh1;
            float gg = a0.z + a1.z + x2 + bh2;
            float go = a0.w + a1.w + x3 + bh3;
            c = sigf(gf) * c + sigf(gi) * tanhfast(gg);
            float h = sigf(go) * tanhfast(c);
            bf16 hh = __float2bfloat16_rn(h);
            bf16 hl = __float2bfloat16_rn(h - __bfloat162float(hh));
            __stcg(&g_he[ph ^ 1][dir][0][b * 256 + u], hh);
            __stcg(&g_he[ph ^ 1][dir][1][b * 256 + u], hl);
            size_t off = ((size_t)t * 64 + b) * 512 + dir * 256 + u;
            yhi[off] = hh; ylo[off] = hl;
            if (step == TT - 1) {
                finh[b * 512 + dir * 256 + u] = h;
                finc[b * 512 + dir * 256 + u] = c;
            }
        }
        tgt += 32;
        mbar(cnt, tgt);
    }
    mbar_reset(cnt, &g_exi[dir][0], 32, (blockIdx.x & 31) == 0);
}

// ---------------------------------------------------------------------------
// Decoder recurrence: 128 CTAs, 4 units/CTA (16 gate cols), ext-K 1536.
// ---------------------------------------------------------------------------
#define DSLOT_W 1280             // 16 rows * 80B
#define DEC_SMEM (32*SLOT_A + 32*DSLOT_W + 8192)   // 212992
__global__ __launch_bounds__(512, 1)
void dec_rec(const float* __restrict__ xg, const float* __restrict__ Whh,
             const float* __restrict__ bhh, const float* __restrict__ h0,
             const float* __restrict__ c0,
             bf16* __restrict__ yhi, bf16* __restrict__ ylo)
{
    extern __shared__ char sm[];
    char* Wb = sm + 32*SLOT_A;
    float* gsh = (float*)(sm + 32*SLOT_A + 32*DSLOT_W);   // [2][1024]
    u32 Au = smem_u32(sm), Wu = smem_u32(Wb);
    int tid = threadIdx.x;
    int u0 = blockIdx.x * 4;

    for (int idx = tid; idx < 16 * 512; idx += 512) {
        int n = idx >> 9, k = idx & 511;
        int grow = (n & 3) * 512 + u0 + (n >> 2);
        float w = Whh[(size_t)grow * 512 + k];
        bf16 h = __float2bfloat16_rn(w);
        int sb = (k >> 5) * DSLOT_W + n * 80 + (k & 31) * 2;
        *(bf16*)(Wb + sb) = h;
        *(bf16*)(Wb + 16*DSLOT_W + sb) = __float2bfloat16_rn(w - __bfloat162float(h));
    }
    int b = (tid & 255) >> 2, ul = tid & 3, u = u0 + ul;
    float bh0 = 0.f, bh1 = 0.f, bh2 = 0.f, bh3 = 0.f, c = 0.f;
    if (tid < 256) {
        bh0 = bhh[u]; bh1 = bhh[512 + u]; bh2 = bhh[1024 + u]; bh3 = bhh[1536 + u];
        c = c0[b * 512 + u];
        float h = h0[b * 512 + u];
        bf16 hh = __float2bfloat16_rn(h);
        __stcg(&g_hd[0][0][b * 512 + u], hh);
        __stcg(&g_hd[0][1][b * 512 + u], __float2bfloat16_rn(h - __bfloat162float(hh)));
    }
    int grp = tid >> 8, w8 = (tid >> 5) & 7, l = tid & 31;
    int wm = w8 >> 1, wn = w8 & 1;
    u32 aoff = (u32)((wm*16 + (l & 15)) * 80 + (l >> 4) * 16);
    u32 boff = (u32)((wn*8 + (l & 7)) * 80 + ((l >> 3) & 1) * 16);
    int t2 = tid & 255, lr = t2 >> 2, lsl = t2 & 3;
    unsigned* cnt = &g_cnt[2][0];
    unsigned tgt = 128;
    mbar(cnt, tgt);                          // h0 visible everywhere

    for (int step = 0; step < TT; step++) {
        int ph = step & 1;
        const bf16* hp0 = g_hd[ph][0];
        const bf16* hp1 = g_hd[ph][1];
#pragma unroll
        for (int it = 0; it < 16; it++) {
            int cidx = grp + it * 2;
            const bf16* hp = (cidx < 16) ? hp0 : hp1;
            int kc = (cidx & 15) * 32;
            cp16(Au + cidx * SLOT_A + lr * 80 + lsl * 16, hp + lr * 512 + kc + lsl * 8);
        }
        asm volatile("cp.async.commit_group;");
        float x0 = 0.f, x1 = 0.f, x2 = 0.f, x3 = 0.f;
        if (tid < 256) {
            const float* xr = xg + ((size_t)step * 64 + b) * 2048 + u;
            x0 = __ldcg(xr);         x1 = __ldcg(xr + 512);
            x2 = __ldcg(xr + 1024);  x3 = __ldcg(xr + 1536);
        }
        asm volatile("cp.async.wait_group 0;");
        __syncthreads();
        float acc[4] = {0.f, 0.f, 0.f, 0.f};
#pragma unroll
        for (int cc = 0; cc < 24; cc++) {
            int cidx = grp * 24 + cc;
            int asl = (cidx < 32) ? cidx : cidx - 32;
            int wsl = (cidx < 16) ? cidx : cidx - 16;
            u32 Aa = Au + asl * SLOT_A + aoff;
            u32 Ba = Wu + wsl * DSLOT_W + boff;
#pragma unroll
            for (int ks = 0; ks < 2; ks++) {
                u32 a[4], bb[2];
                ldsm4(a[0], a[1], a[2], a[3], Aa + ks * 32);
                ldsm2(bb[0], bb[1], Ba + ks * 32);
                mma16816(acc, a, bb);
            }
        }
        {
            float* gs = gsh + grp * 1024;
            int gr = wm * 16 + (l >> 2), gc = wn * 8 + (l & 3) * 2;
            gs[gr*16 + gc] = acc[0];       gs[gr*16 + gc + 1] = acc[1];
            gs[(gr+8)*16 + gc] = acc[2];   gs[(gr+8)*16 + gc + 1] = acc[3];
        }
        __syncthreads();
        if (tid < 256) {
            float4 a0 = *(float4*)&gsh[b * 16 + ul * 4];
            float4 a1 = *(float4*)&gsh[1024 + b * 16 + ul * 4];
            float gi = a0.x + a1.x + x0 + bh0;
            float gf = a0.y + a1.y + x1 + bh1;
            float gg = a0.z + a1.z + x2 + bh2;
            float go = a0.w + a1.w + x3 + bh3;
            c = sigf(gf) * c + sigf(gi) * tanhfast(gg);
            float h = sigf(go) * tanhfast(c);
            bf16 hh = __float2bfloat16_rn(h);
            bf16 hl = __float2bfloat16_rn(h - __bfloat162float(hh));
            __stcg(&g_hd[ph ^ 1][0][b * 512 + u], hh);
            __stcg(&g_hd[ph ^ 1][1][b * 512 + u], hl);
            size_t off = ((size_t)step * 64 + b) * 512 + u;
            yhi[off] = hh; ylo[off] = hl;
        }
        tgt += 128;
        mbar(cnt, tgt);
    }
    mbar_reset(cnt, &g_exi[2][0], 128, blockIdx.x == 0);
}

// ---------------------------------------------------------------------------
// Host launcher
// ---------------------------------------------------------------------------
extern "C" void kernel_launch(void* const* d_in, const int* in_sizes, int n_in,
                              void* d_out, int out_size) {
    (void)in_sizes; (void)n_in; (void)out_size;
    const int*   src     = (const int*)  d_in[0];
    const int*   tgt     = (const int*)  d_in[1];
    const float* src_emb = (const float*)d_in[2];
    const float* tgt_emb = (const float*)d_in[3];
    const float* eWih    = (const float*)d_in[4];
    const float* eWhh    = (const float*)d_in[5];
    const float* ebih    = (const float*)d_in[6];
    const float* ebhh    = (const float*)d_in[7];
    const float* dWih    = (const float*)d_in[8];
    const float* dWhh    = (const float*)d_in[9];
    const float* dbih    = (const float*)d_in[10];
    const float* dbhh    = (const float*)d_in[11];
    const float* linW    = (const float*)d_in[12];
    const float* linb    = (const float*)d_in[13];
    float* out = (float*)d_out;

    cudaFuncSetAttribute(enc_rec, cudaFuncAttributeMaxDynamicSharedMemorySize, ENC_SMEM);
    cudaFuncSetAttribute(dec_rec, cudaFuncAttributeMaxDynamicSharedMemorySize, DEC_SMEM);

    float *pxg, *pfh, *pfc;
    bf16 *pahi, *palo, *pwhi, *pwlo;
    cudaGetSymbolAddress((void**)&pxg,  g_xg);
    cudaGetSymbolAddress((void**)&pfh,  g_finh);
    cudaGetSymbolAddress((void**)&pfc,  g_finc);
    cudaGetSymbolAddress((void**)&pahi, g_ahi);
    cudaGetSymbolAddress((void**)&palo, g_alo);
    cudaGetSymbolAddress((void**)&pwhi, g_whi);
    cudaGetSymbolAddress((void**)&pwlo, g_wlo);

    const int n4_small = 2048 * 512 / 4;
    const int n4_lin   = VT * 512 / 4;

    // ---- encoder layer 1 ----
    gather_split<<<MM, 128>>>(src, src_emb, pahi, palo);
    split_kernel<<<(n4_small + 255) / 256, 256>>>((const float4*)eWih, pwhi, pwlo, n4_small);
    gemm_mma<<<dim3(20, 16), 256>>>(pahi, palo, pwhi, pwlo, ebih, pxg, 2048);
    enc_rec<<<64, 512, ENC_SMEM>>>(pxg, eWhh, ebhh, pahi, palo, pfh, pfc);

    // ---- encoder layer 2 ----
    split_kernel<<<(n4_small + 255) / 256, 256>>>((const float4*)(eWih + 2 * 1024 * 512),
                                                  pwhi, pwlo, n4_small);
    gemm_mma<<<dim3(20, 16), 256>>>(pahi, palo, pwhi, pwlo, ebih + 2048, pxg, 2048);
    enc_rec<<<64, 512, ENC_SMEM>>>(pxg, eWhh + 2 * 1024 * 256, ebhh + 2048,
                                   pahi, palo, pfh + BB * 512, pfc + BB * 512);

    // ---- decoder layer 1 ----
    gather_split<<<MM, 128>>>(tgt, tgt_emb, pahi, palo);
    split_kernel<<<(n4_small + 255) / 256, 256>>>((const float4*)dWih, pwhi, pwlo, n4_small);
    gemm_mma<<<dim3(20, 16), 256>>>(pahi, palo, pwhi, pwlo, dbih, pxg, 2048);
    dec_rec<<<128, 512, DEC_SMEM>>>(pxg, dWhh, dbhh, pfh, pfc, pahi, palo);

    // ---- decoder layer 2 ----
    split_kernel<<<(n4_small + 255) / 256, 256>>>((const float4*)(dWih + 2048 * 512),
                                                  pwhi, pwlo, n4_small);
    gemm_mma<<<dim3(20, 16), 256>>>(pahi, palo, pwhi, pwlo, dbih + 2048, pxg, 2048);
    dec_rec<<<128, 512, DEC_SMEM>>>(pxg, dWhh + 2048 * 512, dbhh + 2048,
                                    pfh + BB * 512, pfc + BB * 512, pahi, palo);

    // ---- output projection ----
    split_kernel<<<(n4_lin + 255) / 256, 256>>>((const float4*)linW, pwhi, pwlo, n4_lin);
    gemm_mma<<<dim3(20, 250), 256>>>(pahi, palo, pwhi, pwlo, linb, out, VT);
}